// round 3
// baseline (speedup 1.0000x reference)
#include <cuda_runtime.h>
#include <math.h>
#include <float.h>

// Problem constants (fixed by setup_inputs)
#define BMAX 2
#define NMAX 8192
#define GMAX 96
#define KMAX 128
#define RAD  0.1f
#define RAD2 0.01f      // float32 nearest to python 0.1*0.1 (matches JAX)
#define CMAXF 8192      // max flattened cells supported (data -> gdprod = 1000)

struct GridInfo {
    float lx, ly, lz;
    int g0, g1, g2;
    int s0, s1;
    int gdprod;
};

struct MM { unsigned mn[3]; unsigned mx[3]; };

__device__ GridInfo g_grid[BMAX];
__device__ MM       g_mm[BMAX];
__device__ int      g_hist[BMAX][CMAXF];
__device__ int      g_ofs[BMAX][CMAXF];
__device__ int      g_cid[BMAX][NMAX];
__device__ int      g_sidx[BMAX][NMAX];
__device__ int      g_idx[BMAX][NMAX];
__device__ float4   g_nlocs[BMAX][NMAX];
__device__ int      g_start[BMAX][CMAXF + 1];

// Monotone float<->uint map (order-preserving for all finite floats)
__device__ __forceinline__ unsigned fenc(float f) {
    unsigned u = __float_as_uint(f);
    return (u & 0x80000000u) ? ~u : (u | 0x80000000u);
}
__device__ __forceinline__ float fdec(unsigned u) {
    unsigned b = (u & 0x80000000u) ? (u & 0x7FFFFFFFu) : ~u;
    return __uint_as_float(b);
}

// Shared helper: grid info from g_mm (deterministic, bit-exact everywhere)
__device__ __forceinline__ void make_grid(int b, float lo[3], int g[3],
                                          int& st0, int& st1, int& gdp) {
    #pragma unroll
    for (int d = 0; d < 3; d++) {
        float l = fdec(g_mm[b].mn[d]);
        float h = fdec(g_mm[b].mx[d]);
        lo[d] = l;
        int gg = (int)floorf(__fdiv_rn(__fsub_rn(h, l), RAD)) + 1;
        g[d] = max(1, min(GMAX, gg));
    }
    st1 = g[2];
    st0 = g[1] * g[2];
    gdp = g[0] * g[1] * g[2];
    if (gdp > CMAXF) gdp = CMAXF;   // never hit for [0,1)^3 data
}

// ---------------------------------------------------------------------------
// K0: reset sentinels + zero histograms
// ---------------------------------------------------------------------------
__global__ void init_kernel()
{
    int t = blockIdx.x * blockDim.x + threadIdx.x;
    int nt = gridDim.x * blockDim.x;
    if (t < BMAX * 3) {
        int b = t / 3, d = t % 3;
        g_mm[b].mn[d] = 0xFFFFFFFFu;
        g_mm[b].mx[d] = 0u;
    }
    for (int c = t; c < BMAX * CMAXF; c += nt)
        ((int*)g_hist)[c] = 0;
}

// ---------------------------------------------------------------------------
// K1: per-batch min/max via encoded atomics (bit-exact min/max)
// ---------------------------------------------------------------------------
__global__ void minmax_kernel(const float* __restrict__ locs, int N)
{
    __shared__ unsigned s_mn[3][16], s_mx[3][16];
    const int b = blockIdx.y;
    const float* L = locs + (size_t)b * N * 3;

    unsigned mn[3] = { ~0u, ~0u, ~0u }, mx[3] = { 0u, 0u, 0u };
    for (int i = blockIdx.x * blockDim.x + threadIdx.x; i < N;
         i += gridDim.x * blockDim.x) {
        #pragma unroll
        for (int d = 0; d < 3; d++) {
            unsigned u = fenc(L[i * 3 + d]);
            mn[d] = min(mn[d], u);
            mx[d] = max(mx[d], u);
        }
    }
    int lane = threadIdx.x & 31, wid = threadIdx.x >> 5;
    #pragma unroll
    for (int d = 0; d < 3; d++) {
        #pragma unroll
        for (int o = 16; o > 0; o >>= 1) {
            mn[d] = min(mn[d], __shfl_down_sync(~0u, mn[d], o));
            mx[d] = max(mx[d], __shfl_down_sync(~0u, mx[d], o));
        }
        if (lane == 0) { s_mn[d][wid] = mn[d]; s_mx[d][wid] = mx[d]; }
    }
    __syncthreads();
    if (threadIdx.x < 3) {
        int d = threadIdx.x;
        unsigned a = ~0u, z = 0u;
        int nw = blockDim.x >> 5;
        for (int w = 0; w < nw; w++) {
            a = min(a, s_mn[d][w]);
            z = max(z, s_mx[d][w]);
        }
        atomicMin(&g_mm[b].mn[d], a);
        atomicMax(&g_mm[b].mx[d], z);
    }
}

// ---------------------------------------------------------------------------
// K2: cell ids + global histogram (1 thread / particle)
// ---------------------------------------------------------------------------
__global__ void cidhist_kernel(const float* __restrict__ locs, int N)
{
    const int b = blockIdx.y;
    const int i = blockIdx.x * blockDim.x + threadIdx.x;
    float lo[3]; int g[3], st0, st1, gdp;
    make_grid(b, lo, g, st0, st1, gdp);

    if (blockIdx.x == 0 && threadIdx.x == 0) {
        GridInfo gi;
        gi.lx = lo[0]; gi.ly = lo[1]; gi.lz = lo[2];
        gi.g0 = g[0]; gi.g1 = g[1]; gi.g2 = g[2];
        gi.s0 = st0; gi.s1 = st1; gi.gdprod = gdp;
        g_grid[b] = gi;
    }
    if (i >= N) return;

    const float* p = locs + ((size_t)b * N + i) * 3;
    int c[3];
    #pragma unroll
    for (int d = 0; d < 3; d++) {
        int cc = (int)floorf(__fdiv_rn(__fsub_rn(p[d], lo[d]), RAD));
        c[d] = max(0, min(g[d] - 1, cc));
    }
    int cid = c[0] * st0 + c[1] * st1 + c[2];
    if (cid >= gdp) cid = gdp - 1;  // only reachable if gdp was clamped
    g_cid[b][i] = cid;
    atomicAdd(&g_hist[b][cid], 1);
}

// ---------------------------------------------------------------------------
// K3: exclusive scan over bins -> g_start (+tail), g_ofs. One block / batch.
// ---------------------------------------------------------------------------
__global__ __launch_bounds__(1024)
void scan_kernel(int N)
{
    __shared__ int s_bins[CMAXF];
    __shared__ int s_part[1024];
    const int b = blockIdx.x;
    const int t = threadIdx.x;
    const int gdp = g_grid[b].gdprod;

    const int E = (gdp + 1023) >> 10;   // <= 8
    int vals[8];
    int base = t * E;
    int sum = 0;
    #pragma unroll 8
    for (int e = 0; e < 8; e++) {
        int c = base + e;
        int v = (e < E && c < gdp) ? g_hist[b][c] : 0;
        vals[e] = v; sum += v;
    }
    s_part[t] = sum;
    __syncthreads();
    for (int off = 1; off < 1024; off <<= 1) {
        int v = (t >= off) ? s_part[t - off] : 0;
        __syncthreads();
        s_part[t] += v;
        __syncthreads();
    }
    int run = s_part[t] - sum;
    #pragma unroll 8
    for (int e = 0; e < 8; e++) {
        int c = base + e;
        if (e < E && c < gdp) { s_bins[c] = run; run += vals[e]; }
    }
    __syncthreads();
    for (int c = t; c <= CMAXF; c += 1024) {
        int v = (c < gdp) ? s_bins[c] : N;
        g_start[b][c] = v;
        if (c < gdp) g_ofs[b][c] = v;
    }
}

// ---------------------------------------------------------------------------
// K4: scatter (unordered within cell)
// ---------------------------------------------------------------------------
__global__ void scatter_kernel(int N)
{
    const int b = blockIdx.y;
    const int i = blockIdx.x * blockDim.x + threadIdx.x;
    if (i >= N) return;
    int cid = g_cid[b][i];
    int pos = atomicAdd(&g_ofs[b][cid], 1);
    g_sidx[b][pos] = i;
}

// ---------------------------------------------------------------------------
// K5: per-cell stable fixup (insertion sort by original index) + emit
// ---------------------------------------------------------------------------
__global__ void fixemit_kernel(const float* __restrict__ locs,
                               float* __restrict__ out_idxs,
                               float* __restrict__ out_nlocs, int N)
{
    const int b = blockIdx.y;
    const int c = blockIdx.x * blockDim.x + threadIdx.x;
    const int gdp = g_grid[b].gdprod;
    if (c >= gdp) return;

    int lo = g_start[b][c], hi = g_start[b][c + 1];
    int* s = g_sidx[b];
    for (int i = lo + 1; i < hi; i++) {
        int v = s[i];
        int j = i - 1;
        while (j >= lo && s[j] > v) { s[j + 1] = s[j]; j--; }
        s[j + 1] = v;
    }
    const float* L = locs + (size_t)b * N * 3;
    for (int pos = lo; pos < hi; pos++) {
        int i = s[pos];
        g_idx[b][pos] = i;
        out_idxs[(size_t)b * N + pos] = (float)i;
        float x = L[i * 3 + 0], y = L[i * 3 + 1], z = L[i * 3 + 2];
        float* o = out_nlocs + ((size_t)b * N + pos) * 3;
        o[0] = x; o[1] = y; o[2] = z;
        g_nlocs[b][pos] = make_float4(x, y, z, 0.f);
    }
}

// ---------------------------------------------------------------------------
// Gather reordered data rows; 4 float4s per thread, idx amortized.
// ---------------------------------------------------------------------------
__global__ void gather_data_kernel(const float4* __restrict__ data,
                                   float4* __restrict__ out, int B, int N, int C4)
{
    int Q = C4 >> 2;                       // float4-quads per row
    int t = blockIdx.x * blockDim.x + threadIdx.x;
    if (t >= B * N * Q) return;
    int sub = t % Q;
    int bi  = t / Q;
    int b = bi / N, i = bi - b * N;
    int idx = __ldg(&g_idx[b][i]);
    const float4* src = data + (((size_t)b * N + idx) * C4) + sub * 4;
    float4* dst = out + ((size_t)bi * C4) + sub * 4;
    float4 v0 = src[0], v1 = src[1], v2 = src[2], v3 = src[3];
    dst[0] = v0; dst[1] = v1; dst[2] = v2; dst[3] = v3;
}

// ---------------------------------------------------------------------------
// Collision: one warp per query (unchanged from R2 — exact ordered append).
// ---------------------------------------------------------------------------
__global__ void collide_kernel(const float* __restrict__ qlocs,
                               float* __restrict__ out_nb, int B, int M)
{
    int gt   = blockIdx.x * blockDim.x + threadIdx.x;
    int w    = gt >> 5;
    int lane = gt & 31;
    if (w >= B * M) return;
    int b = w / M, m = w - b * M;

    const float* q = qlocs + ((size_t)b * M + m) * 3;
    float qx = q[0], qy = q[1], qz = q[2];

    GridInfo gi = g_grid[b];
    int cqx = (int)floorf(__fdiv_rn(__fsub_rn(qx, gi.lx), RAD));
    int cqy = (int)floorf(__fdiv_rn(__fsub_rn(qy, gi.ly), RAD));
    int cqz = (int)floorf(__fdiv_rn(__fsub_rn(qz, gi.lz), RAD));
    int z0 = max(0, cqz - 1), z1 = min(gi.g2 - 1, cqz + 1);

    const int* __restrict__ S = g_start[b];
    const float4* __restrict__ P = g_nlocs[b];
    float* outp = out_nb + (size_t)w * KMAX;

    int jlo[9], jhi[9];
    bool zok = (z0 <= z1);
    #pragma unroll
    for (int r = 0; r < 9; r++) {
        int cx = cqx + (r / 3) - 1;
        int cy = cqy + (r % 3) - 1;
        bool ok = zok && cx >= 0 && cx < gi.g0 && cy >= 0 && cy < gi.g1;
        int base = cx * gi.s0 + cy * gi.s1;
        jlo[r] = ok ? S[base + z0] : 0;
        jhi[r] = ok ? S[base + z1 + 1] : 0;
    }

    int cnt = 0;
    bool done = false;
    #pragma unroll
    for (int r = 0; r < 9; r++) {
        int lo = jlo[r], hi = jhi[r];
        for (int j0 = lo; j0 < hi && !done; j0 += 32) {
            int j = j0 + lane;
            bool hit = false;
            if (j < hi) {
                float4 p = P[j];
                float dx = __fsub_rn(qx, p.x);
                float dy = __fsub_rn(qy, p.y);
                float dz = __fsub_rn(qz, p.z);
                float d2 = __fadd_rn(__fadd_rn(__fmul_rn(dx, dx),
                                               __fmul_rn(dy, dy)),
                                     __fmul_rn(dz, dz));
                hit = (d2 <= RAD2);
            }
            unsigned msk = __ballot_sync(0xffffffffu, hit);
            if (hit) {
                int pos = cnt + __popc(msk & ((1u << lane) - 1u));
                if (pos < KMAX) outp[pos] = (float)j;
            }
            cnt += __popc(msk);
            if (cnt >= KMAX) { cnt = KMAX; done = true; }
        }
        if (done) break;
    }
    for (int p = cnt + lane; p < KMAX; p += 32) outp[p] = -1.0f;
}

// ---------------------------------------------------------------------------
extern "C" void kernel_launch(void* const* d_in, const int* in_sizes, int n_in,
                              void* d_out, int out_size)
{
    const float* locs  = (const float*)d_in[0];
    const float* data  = (const float*)d_in[1];
    const float* qlocs = (const float*)d_in[2];

    const int B = 2;                       // fixed by setup_inputs
    const int N = in_sizes[0] / (B * 3);
    const int C = in_sizes[1] / (B * N);
    const int M = in_sizes[2] / (B * 3);
    if (N > NMAX || B > BMAX) return;      // scratch bound guard (never hit)

    float* out       = (float*)d_out;
    float* out_nlocs = out;
    float* out_ndata = out_nlocs + (size_t)B * N * 3;
    float* out_idxs  = out_ndata + (size_t)B * N * C;
    float* out_nb    = out_idxs  + (size_t)B * N;

    init_kernel<<<32, 512>>>();

    minmax_kernel<<<dim3(8, B), 256>>>(locs, N);

    cidhist_kernel<<<dim3((N + 511) / 512, B), 512>>>(locs, N);

    scan_kernel<<<B, 1024>>>(N);

    scatter_kernel<<<dim3((N + 511) / 512, B), 512>>>(N);

    fixemit_kernel<<<dim3((CMAXF + 255) / 256, B), 256>>>(locs, out_idxs,
                                                          out_nlocs, N);

    int C4 = C / 4;
    int tg = B * N * (C4 / 4);
    gather_data_kernel<<<(tg + 255) / 256, 256>>>((const float4*)data,
                                                  (float4*)out_ndata, B, N, C4);

    int nth = B * M * 32;
    collide_kernel<<<(nth + 255) / 256, 256>>>(qlocs, out_nb, B, M);
}

// round 4
// speedup vs baseline: 1.3691x; 1.3691x over previous
#include <cuda_runtime.h>
#include <math.h>
#include <float.h>

// Problem constants (fixed by setup_inputs)
#define BMAX 2
#define NMAX 8192
#define GMAX 96
#define KMAX 128
#define RAD  0.1f
#define RAD2 0.01f      // float32 nearest to python 0.1*0.1 (matches JAX)
#define CMAXF 8192      // max flattened cells supported (data -> gdprod = 1000)

struct GridInfo {
    float lx, ly, lz;
    int g0, g1, g2;
    int s0, s1;
    int gdprod;
};

__device__ GridInfo g_grid[BMAX];
__device__ int      g_idx[BMAX][NMAX];
__device__ float4   g_nlocs[BMAX][NMAX];
__device__ int      g_start[BMAX][CMAXF + 1];

// ---------------------------------------------------------------------------
// Fused sort kernel: one block per batch, 1024 threads.
// Phases: shuffle-minmax (2 syncs) -> cid+hist -> shuffle-scan (3 syncs,
// fast path gdp<=1024) -> scatter -> per-cell stable insertion fixup -> emit.
// smem: cid[N] | idx[N] | start[CMAXF+1] | ofs[CMAXF]   (~128KB dynamic)
// ---------------------------------------------------------------------------
__global__ __launch_bounds__(1024)
void sort_kernel(const float* __restrict__ locs,
                 float* __restrict__ out_idxs,
                 float* __restrict__ out_nlocs,
                 int N)
{
    extern __shared__ int sh[];
    int* s_cid   = sh;                       // [NMAX]
    int* s_idx   = s_cid + NMAX;             // [NMAX]
    int* s_start = s_idx + NMAX;             // [CMAXF+1]
    int* s_ofs   = s_start + (CMAXF + 1);    // [CMAXF]

    __shared__ float s_wmn[32][3], s_wmx[32][3];
    __shared__ int   s_part[1024];
    __shared__ float s_lo[3], s_hi[3];

    const int b = blockIdx.x;
    const int t = threadIdx.x;
    const int lane = t & 31;
    const int wid  = t >> 5;
    const float* L = locs + (size_t)b * N * 3;

    // ---- 1) min/max: warp shuffles, 2 syncs ----
    float mn[3] = { FLT_MAX, FLT_MAX, FLT_MAX };
    float mx[3] = { -FLT_MAX, -FLT_MAX, -FLT_MAX };
    for (int i = t; i < N; i += 1024) {
        #pragma unroll
        for (int d = 0; d < 3; d++) {
            float v = L[i * 3 + d];
            mn[d] = fminf(mn[d], v);
            mx[d] = fmaxf(mx[d], v);
        }
    }
    #pragma unroll
    for (int d = 0; d < 3; d++) {
        #pragma unroll
        for (int o = 16; o > 0; o >>= 1) {
            mn[d] = fminf(mn[d], __shfl_down_sync(0xffffffffu, mn[d], o));
            mx[d] = fmaxf(mx[d], __shfl_down_sync(0xffffffffu, mx[d], o));
        }
        if (lane == 0) { s_wmn[wid][d] = mn[d]; s_wmx[wid][d] = mx[d]; }
    }
    __syncthreads();
    if (wid == 0) {
        float a[3], z[3];
        #pragma unroll
        for (int d = 0; d < 3; d++) { a[d] = s_wmn[lane][d]; z[d] = s_wmx[lane][d]; }
        #pragma unroll
        for (int d = 0; d < 3; d++) {
            #pragma unroll
            for (int o = 16; o > 0; o >>= 1) {
                a[d] = fminf(a[d], __shfl_down_sync(0xffffffffu, a[d], o));
                z[d] = fmaxf(z[d], __shfl_down_sync(0xffffffffu, z[d], o));
            }
            if (lane == 0) { s_lo[d] = a[d]; s_hi[d] = z[d]; }
        }
    }
    __syncthreads();

    // grid info (all threads compute redundantly; deterministic)
    int g[3];
    #pragma unroll
    for (int d = 0; d < 3; d++) {
        int gg = (int)floorf(__fdiv_rn(__fsub_rn(s_hi[d], s_lo[d]), RAD)) + 1;
        g[d] = max(1, min(GMAX, gg));
    }
    const int st1 = g[2];
    const int st0 = g[1] * g[2];
    int gdp = g[0] * g[1] * g[2];
    if (gdp > CMAXF) gdp = CMAXF;       // never hit for [0,1)^3 data
    if (t == 0) {
        GridInfo gi;
        gi.lx = s_lo[0]; gi.ly = s_lo[1]; gi.lz = s_lo[2];
        gi.g0 = g[0]; gi.g1 = g[1]; gi.g2 = g[2];
        gi.s0 = st0; gi.s1 = st1; gi.gdprod = gdp;
        g_grid[b] = gi;
    }

    // ---- 2) zero bins, cell ids, histogram ----
    for (int c = t; c < gdp; c += 1024) s_start[c] = 0;
    __syncthreads();
    for (int i = t; i < N; i += 1024) {
        int c[3];
        #pragma unroll
        for (int d = 0; d < 3; d++) {
            float v = L[i * 3 + d];
            int cc = (int)floorf(__fdiv_rn(__fsub_rn(v, s_lo[d]), RAD));
            cc = max(0, min(g[d] - 1, cc));
            c[d] = cc;
        }
        int cid = c[0] * st0 + c[1] * st1 + c[2];
        if (cid >= gdp) cid = gdp - 1;  // only if gdp was clamped
        s_cid[i] = cid;
        atomicAdd(&s_start[cid], 1);
    }
    __syncthreads();

    // ---- 3) exclusive scan ----
    if (gdp <= 1024) {
        // fast path: 2-level warp shuffle scan, 3 syncs
        int v = (t < gdp) ? s_start[t] : 0;
        int x = v;
        #pragma unroll
        for (int o = 1; o < 32; o <<= 1) {
            int y = __shfl_up_sync(0xffffffffu, x, o);
            if (lane >= o) x += y;
        }
        if (lane == 31) s_part[wid] = x;
        __syncthreads();
        if (wid == 0) {
            int w = s_part[lane];
            int xw = w;
            #pragma unroll
            for (int o = 1; o < 32; o <<= 1) {
                int y = __shfl_up_sync(0xffffffffu, xw, o);
                if (lane >= o) xw += y;
            }
            s_part[lane] = xw - w;   // exclusive warp offset
        }
        __syncthreads();
        int excl = x - v + s_part[wid];
        if (t < gdp) { s_start[t] = excl; s_ofs[t] = excl; }
        if (t == 0) s_start[gdp] = N;
        __syncthreads();
    } else {
        // general path (Hillis-Steele over thread chunks)
        const int E = (gdp + 1023) >> 10;
        int vals[8];
        int base = t * E;
        int sum = 0;
        #pragma unroll 8
        for (int e = 0; e < 8; e++) {
            int c = base + e;
            int v = (e < E && c < gdp) ? s_start[c] : 0;
            vals[e] = v; sum += v;
        }
        s_part[t] = sum;
        __syncthreads();
        for (int off = 1; off < 1024; off <<= 1) {
            int v = (t >= off) ? s_part[t - off] : 0;
            __syncthreads();
            s_part[t] += v;
            __syncthreads();
        }
        int run = s_part[t] - sum;
        #pragma unroll 8
        for (int e = 0; e < 8; e++) {
            int c = base + e;
            if (e < E && c < gdp) { s_start[c] = run; s_ofs[c] = run; run += vals[e]; }
        }
        if (t == 0) s_start[gdp] = N;
        __syncthreads();
    }

    // emit g_start (+ tail as N so collide lookups are always safe)
    for (int c = t; c <= CMAXF; c += 1024)
        g_start[b][c] = (c <= gdp) ? s_start[c] : N;

    // ---- 4) scatter (unordered within cell) ----
    for (int i = t; i < N; i += 1024) {
        int pos = atomicAdd(&s_ofs[s_cid[i]], 1);
        s_idx[pos] = i;
    }
    __syncthreads();

    // ---- 5) per-cell insertion sort by original index => exact STABLE ----
    for (int c = t; c < gdp; c += 1024) {
        int lo = s_start[c], hi = s_start[c + 1];
        for (int i = lo + 1; i < hi; i++) {
            int v = s_idx[i];
            int j = i - 1;
            while (j >= lo && s_idx[j] > v) { s_idx[j + 1] = s_idx[j]; j--; }
            s_idx[j + 1] = v;
        }
    }
    __syncthreads();

    // ---- 6) emit idxs + gathered locs ----
    for (int pos = t; pos < N; pos += 1024) {
        int i = s_idx[pos];
        g_idx[b][pos] = i;
        out_idxs[(size_t)b * N + pos] = (float)i;
        const float* p = L + (size_t)i * 3;
        float x = p[0], y = p[1], z = p[2];
        float* o = out_nlocs + ((size_t)b * N + pos) * 3;
        o[0] = x; o[1] = y; o[2] = z;
        g_nlocs[b][pos] = make_float4(x, y, z, 0.f);
    }
}

// ---------------------------------------------------------------------------
// Fused tail: collide blocks first (longer-running), then gather blocks.
// The two workloads are independent; fusing saves a graph node and overlaps
// them across the chip.
// ---------------------------------------------------------------------------
__global__ void tail_kernel(const float4* __restrict__ data,
                            const float* __restrict__ qlocs,
                            float4* __restrict__ out_ndata,
                            float* __restrict__ out_nb,
                            int B, int N, int C4, int M, int collideBlocks)
{
    if ((int)blockIdx.x >= collideBlocks) {
        // ---------------- gather: 4 float4s per thread ----------------
        int Q = C4 >> 2;
        int t = (blockIdx.x - collideBlocks) * blockDim.x + threadIdx.x;
        if (t >= B * N * Q) return;
        int sub = t % Q;
        int bi  = t / Q;
        int b = bi / N, i = bi - b * N;
        int idx = __ldg(&g_idx[b][i]);
        const float4* src = data + (((size_t)b * N + idx) * C4) + sub * 4;
        float4* dst = out_ndata + ((size_t)bi * C4) + sub * 4;
        float4 v0 = src[0], v1 = src[1], v2 = src[2], v3 = src[3];
        dst[0] = v0; dst[1] = v1; dst[2] = v2; dst[3] = v3;
        return;
    }

    // ---------------- collide: one warp per query ----------------
    int gt   = blockIdx.x * blockDim.x + threadIdx.x;
    int w    = gt >> 5;
    int lane = gt & 31;
    if (w >= B * M) return;
    int b = w / M, m = w - b * M;

    const float* q = qlocs + ((size_t)b * M + m) * 3;
    float qx = q[0], qy = q[1], qz = q[2];

    GridInfo gi = g_grid[b];
    int cqx = (int)floorf(__fdiv_rn(__fsub_rn(qx, gi.lx), RAD));
    int cqy = (int)floorf(__fdiv_rn(__fsub_rn(qy, gi.ly), RAD));
    int cqz = (int)floorf(__fdiv_rn(__fsub_rn(qz, gi.lz), RAD));
    int z0 = max(0, cqz - 1), z1 = min(gi.g2 - 1, cqz + 1);

    const int* __restrict__ S = g_start[b];
    const float4* __restrict__ P = g_nlocs[b];
    float* outp = out_nb + (size_t)w * KMAX;

    int jlo[9], jhi[9];
    bool zok = (z0 <= z1);
    #pragma unroll
    for (int r = 0; r < 9; r++) {
        int cx = cqx + (r / 3) - 1;
        int cy = cqy + (r % 3) - 1;
        bool ok = zok && cx >= 0 && cx < gi.g0 && cy >= 0 && cy < gi.g1;
        int base = cx * gi.s0 + cy * gi.s1;
        jlo[r] = ok ? S[base + z0] : 0;
        jhi[r] = ok ? S[base + z1 + 1] : 0;
    }

    int cnt = 0;
    bool done = false;
    #pragma unroll
    for (int r = 0; r < 9; r++) {
        int lo = jlo[r], hi = jhi[r];
        for (int j0 = lo; j0 < hi && !done; j0 += 32) {
            int j = j0 + lane;
            bool hit = false;
            if (j < hi) {
                float4 p = P[j];
                float dx = __fsub_rn(qx, p.x);
                float dy = __fsub_rn(qy, p.y);
                float dz = __fsub_rn(qz, p.z);
                float d2 = __fadd_rn(__fadd_rn(__fmul_rn(dx, dx),
                                               __fmul_rn(dy, dy)),
                                     __fmul_rn(dz, dz));
                hit = (d2 <= RAD2);
            }
            unsigned msk = __ballot_sync(0xffffffffu, hit);
            if (hit) {
                int pos = cnt + __popc(msk & ((1u << lane) - 1u));
                if (pos < KMAX) outp[pos] = (float)j;
            }
            cnt += __popc(msk);
            if (cnt >= KMAX) { cnt = KMAX; done = true; }
        }
        if (done) break;
    }
    for (int p = cnt + lane; p < KMAX; p += 32) outp[p] = -1.0f;
}

// ---------------------------------------------------------------------------
extern "C" void kernel_launch(void* const* d_in, const int* in_sizes, int n_in,
                              void* d_out, int out_size)
{
    const float* locs  = (const float*)d_in[0];
    const float* data  = (const float*)d_in[1];
    const float* qlocs = (const float*)d_in[2];

    const int B = 2;                       // fixed by setup_inputs
    const int N = in_sizes[0] / (B * 3);
    const int C = in_sizes[1] / (B * N);
    const int M = in_sizes[2] / (B * 3);
    if (N > NMAX || B > BMAX) return;      // scratch bound guard (never hit)

    float* out       = (float*)d_out;
    float* out_nlocs = out;
    float* out_ndata = out_nlocs + (size_t)B * N * 3;
    float* out_idxs  = out_ndata + (size_t)B * N * C;
    float* out_nb    = out_idxs  + (size_t)B * N;

    size_t smem = (size_t)(NMAX * 2 + (CMAXF + 1) + CMAXF) * sizeof(int);
    cudaFuncSetAttribute(sort_kernel,
                         cudaFuncAttributeMaxDynamicSharedMemorySize, (int)smem);
    sort_kernel<<<B, 1024, smem>>>(locs, out_idxs, out_nlocs, N);

    const int TPB = 256;
    int C4 = C / 4;
    int Q  = C4 / 4;
    int collideBlocks = (B * M * 32 + TPB - 1) / TPB;
    int gatherBlocks  = (B * N * Q + TPB - 1) / TPB;
    tail_kernel<<<collideBlocks + gatherBlocks, TPB>>>(
        (const float4*)data, qlocs, (float4*)out_ndata, out_nb,
        B, N, C4, M, collideBlocks);
}

// round 5
// speedup vs baseline: 1.5016x; 1.0968x over previous
#include <cuda_runtime.h>
#include <math.h>
#include <float.h>

// Problem constants (fixed by setup_inputs)
#define BMAX 2
#define NMAX 8192
#define GMAX 96
#define KMAX 128
#define RAD  0.1f
#define RAD2 0.01f      // float32 nearest to python 0.1*0.1 (matches JAX)
#define CMAXF 8192      // max flattened cells supported (data -> gdprod = 1000)

struct GridInfo {
    float lx, ly, lz;
    int g0, g1, g2;
    int s0, s1;
    int gdprod;
};

__device__ GridInfo g_grid[BMAX];
__device__ int      g_idx[BMAX][NMAX];
__device__ float4   g_nlocs[BMAX][NMAX];
__device__ int      g_start[BMAX][CMAXF + 1];

// ---------------------------------------------------------------------------
// Fused sort kernel: one block per batch, 1024 threads.
// locs staged in smem ONCE (coalesced float4) -> all later passes are LDS.
// smem: loc[3N] | cid[N] | idx[N] | start[CMAXF+1]  (~192KB dynamic)
// ---------------------------------------------------------------------------
__global__ __launch_bounds__(1024)
void sort_kernel(const float* __restrict__ locs,
                 float* __restrict__ out_idxs,
                 float* __restrict__ out_nlocs,
                 int N)
{
    extern __shared__ float shf[];
    float* s_loc  = shf;                          // [NMAX*3]
    int*  s_cid   = (int*)(s_loc + NMAX * 3);     // [NMAX]
    int*  s_idx   = s_cid + NMAX;                 // [NMAX]
    int*  s_start = s_idx + NMAX;                 // [CMAXF+1]
    int*  s_part  = s_idx;                        // alias: scan partials

    __shared__ float s_wmn[32][3], s_wmx[32][3];
    __shared__ float s_lo[3], s_hi[3];

    const int b = blockIdx.x;
    const int t = threadIdx.x;
    const int lane = t & 31;
    const int wid  = t >> 5;

    // ---- 0) stage locs into smem, coalesced float4 ----
    {
        const float* Lg = locs + (size_t)b * N * 3;
        int n4 = (N * 3) >> 2;
        const float4* L4 = (const float4*)Lg;
        float4* S4 = (float4*)s_loc;
        for (int k = t; k < n4; k += 1024) S4[k] = L4[k];
        for (int k = (n4 << 2) + t; k < N * 3; k += 1024) s_loc[k] = Lg[k];
    }
    __syncthreads();

    // ---- 1) min/max from smem, warp shuffles ----
    float mn[3] = { FLT_MAX, FLT_MAX, FLT_MAX };
    float mx[3] = { -FLT_MAX, -FLT_MAX, -FLT_MAX };
    for (int i = t; i < N; i += 1024) {
        #pragma unroll
        for (int d = 0; d < 3; d++) {
            float v = s_loc[i * 3 + d];
            mn[d] = fminf(mn[d], v);
            mx[d] = fmaxf(mx[d], v);
        }
    }
    #pragma unroll
    for (int d = 0; d < 3; d++) {
        #pragma unroll
        for (int o = 16; o > 0; o >>= 1) {
            mn[d] = fminf(mn[d], __shfl_down_sync(0xffffffffu, mn[d], o));
            mx[d] = fmaxf(mx[d], __shfl_down_sync(0xffffffffu, mx[d], o));
        }
        if (lane == 0) { s_wmn[wid][d] = mn[d]; s_wmx[wid][d] = mx[d]; }
    }
    __syncthreads();
    if (wid == 0) {
        float a[3], z[3];
        #pragma unroll
        for (int d = 0; d < 3; d++) { a[d] = s_wmn[lane][d]; z[d] = s_wmx[lane][d]; }
        #pragma unroll
        for (int d = 0; d < 3; d++) {
            #pragma unroll
            for (int o = 16; o > 0; o >>= 1) {
                a[d] = fminf(a[d], __shfl_down_sync(0xffffffffu, a[d], o));
                z[d] = fmaxf(z[d], __shfl_down_sync(0xffffffffu, z[d], o));
            }
            if (lane == 0) { s_lo[d] = a[d]; s_hi[d] = z[d]; }
        }
    }
    __syncthreads();

    // grid info (redundant per-thread; deterministic)
    int g[3];
    #pragma unroll
    for (int d = 0; d < 3; d++) {
        int gg = (int)floorf(__fdiv_rn(__fsub_rn(s_hi[d], s_lo[d]), RAD)) + 1;
        g[d] = max(1, min(GMAX, gg));
    }
    const int st1 = g[2];
    const int st0 = g[1] * g[2];
    int gdp = g[0] * g[1] * g[2];
    if (gdp > CMAXF) gdp = CMAXF;       // never hit for [0,1)^3 data
    if (t == 0) {
        GridInfo gi;
        gi.lx = s_lo[0]; gi.ly = s_lo[1]; gi.lz = s_lo[2];
        gi.g0 = g[0]; gi.g1 = g[1]; gi.g2 = g[2];
        gi.s0 = st0; gi.s1 = st1; gi.gdprod = gdp;
        g_grid[b] = gi;
    }

    // ---- 2) zero bins, cell ids, histogram (all from smem) ----
    for (int c = t; c < gdp; c += 1024) s_start[c] = 0;
    __syncthreads();
    for (int i = t; i < N; i += 1024) {
        int c[3];
        #pragma unroll
        for (int d = 0; d < 3; d++) {
            float v = s_loc[i * 3 + d];
            int cc = (int)floorf(__fdiv_rn(__fsub_rn(v, s_lo[d]), RAD));
            cc = max(0, min(g[d] - 1, cc));
            c[d] = cc;
        }
        int cid = c[0] * st0 + c[1] * st1 + c[2];
        if (cid >= gdp) cid = gdp - 1;  // only if gdp was clamped
        s_cid[i] = cid;
        atomicAdd(&s_start[cid], 1);
    }
    __syncthreads();

    // ---- 3) exclusive scan ----
    if (gdp <= 1024) {
        int v = (t < gdp) ? s_start[t] : 0;
        int x = v;
        #pragma unroll
        for (int o = 1; o < 32; o <<= 1) {
            int y = __shfl_up_sync(0xffffffffu, x, o);
            if (lane >= o) x += y;
        }
        if (lane == 31) s_part[wid] = x;
        __syncthreads();
        if (wid == 0) {
            int w = s_part[lane];
            int xw = w;
            #pragma unroll
            for (int o = 1; o < 32; o <<= 1) {
                int y = __shfl_up_sync(0xffffffffu, xw, o);
                if (lane >= o) xw += y;
            }
            s_part[lane] = xw - w;   // exclusive warp offset
        }
        __syncthreads();
        int excl = x - v + s_part[wid];
        __syncthreads();           // s_part reads done before s_idx reuse later
        if (t < gdp) s_start[t] = excl;
        if (t == 0) s_start[gdp] = N;
        __syncthreads();
    } else {
        const int E = (gdp + 1023) >> 10;
        int vals[8];
        int base = t * E;
        int sum = 0;
        #pragma unroll 8
        for (int e = 0; e < 8; e++) {
            int c = base + e;
            int v = (e < E && c < gdp) ? s_start[c] : 0;
            vals[e] = v; sum += v;
        }
        s_part[t] = sum;
        __syncthreads();
        for (int off = 1; off < 1024; off <<= 1) {
            int v = (t >= off) ? s_part[t - off] : 0;
            __syncthreads();
            s_part[t] += v;
            __syncthreads();
        }
        int run = s_part[t] - sum;
        #pragma unroll 8
        for (int e = 0; e < 8; e++) {
            int c = base + e;
            if (e < E && c < gdp) { s_start[c] = run; run += vals[e]; }
        }
        if (t == 0) s_start[gdp] = N;
        __syncthreads();
    }

    // emit g_start (+ tail as N so collide lookups are always safe)
    for (int c = t; c <= CMAXF; c += 1024)
        g_start[b][c] = (c <= gdp) ? s_start[c] : N;
    __syncthreads();

    // ---- 4) scatter directly on s_start: afterwards s_start[c] = start[c+1]
    for (int i = t; i < N; i += 1024) {
        int pos = atomicAdd(&s_start[s_cid[i]], 1);
        s_idx[pos] = i;
    }
    __syncthreads();

    // ---- 5) per-cell insertion sort by original index => exact STABLE ----
    for (int c = t; c < gdp; c += 1024) {
        int lo = (c == 0) ? 0 : s_start[c - 1];
        int hi = s_start[c];
        for (int i = lo + 1; i < hi; i++) {
            int v = s_idx[i];
            int j = i - 1;
            while (j >= lo && s_idx[j] > v) { s_idx[j + 1] = s_idx[j]; j--; }
            s_idx[j + 1] = v;
        }
    }
    __syncthreads();

    // ---- 6) emit idxs + gathered locs (random reads are LDS now) ----
    for (int pos = t; pos < N; pos += 1024) {
        int i = s_idx[pos];
        g_idx[b][pos] = i;
        out_idxs[(size_t)b * N + pos] = (float)i;
        float x = s_loc[i * 3 + 0];
        float y = s_loc[i * 3 + 1];
        float z = s_loc[i * 3 + 2];
        float* o = out_nlocs + ((size_t)b * N + pos) * 3;
        o[0] = x; o[1] = y; o[2] = z;
        g_nlocs[b][pos] = make_float4(x, y, z, 0.f);
    }
}

// ---------------------------------------------------------------------------
// Fused tail: collide blocks first (longer-running), then gather blocks.
// ---------------------------------------------------------------------------
__global__ void tail_kernel(const float4* __restrict__ data,
                            const float* __restrict__ qlocs,
                            float4* __restrict__ out_ndata,
                            float* __restrict__ out_nb,
                            int B, int N, int C4, int M, int collideBlocks)
{
    if ((int)blockIdx.x >= collideBlocks) {
        // ---------------- gather: 4 float4s per thread ----------------
        int Q = C4 >> 2;
        int t = (blockIdx.x - collideBlocks) * blockDim.x + threadIdx.x;
        if (t >= B * N * Q) return;
        int sub = t % Q;
        int bi  = t / Q;
        int b = bi / N, i = bi - b * N;
        int idx = __ldg(&g_idx[b][i]);
        const float4* src = data + (((size_t)b * N + idx) * C4) + sub * 4;
        float4* dst = out_ndata + ((size_t)bi * C4) + sub * 4;
        float4 v0 = src[0], v1 = src[1], v2 = src[2], v3 = src[3];
        dst[0] = v0; dst[1] = v1; dst[2] = v2; dst[3] = v3;
        return;
    }

    // ---------------- collide: one warp per query ----------------
    int gt   = blockIdx.x * blockDim.x + threadIdx.x;
    int w    = gt >> 5;
    int lane = gt & 31;
    if (w >= B * M) return;
    int b = w / M, m = w - b * M;

    const float* q = qlocs + ((size_t)b * M + m) * 3;
    float qx = q[0], qy = q[1], qz = q[2];

    GridInfo gi = g_grid[b];
    int cqx = (int)floorf(__fdiv_rn(__fsub_rn(qx, gi.lx), RAD));
    int cqy = (int)floorf(__fdiv_rn(__fsub_rn(qy, gi.ly), RAD));
    int cqz = (int)floorf(__fdiv_rn(__fsub_rn(qz, gi.lz), RAD));
    int z0 = max(0, cqz - 1), z1 = min(gi.g2 - 1, cqz + 1);

    const int* __restrict__ S = g_start[b];
    const float4* __restrict__ P = g_nlocs[b];
    float* outp = out_nb + (size_t)w * KMAX;

    // prefill whole row with -1 (one float4 per lane), then overwrite hits
    ((float4*)outp)[lane] = make_float4(-1.f, -1.f, -1.f, -1.f);
    __syncwarp();

    int jlo[9], jhi[9];
    bool zok = (z0 <= z1);
    #pragma unroll
    for (int r = 0; r < 9; r++) {
        int cx = cqx + (r / 3) - 1;
        int cy = cqy + (r % 3) - 1;
        bool ok = zok && cx >= 0 && cx < gi.g0 && cy >= 0 && cy < gi.g1;
        int base = cx * gi.s0 + cy * gi.s1;
        jlo[r] = ok ? S[base + z0] : 0;
        jhi[r] = ok ? S[base + z1 + 1] : 0;
    }

    int cnt = 0;
    bool done = false;
    #pragma unroll
    for (int r = 0; r < 9; r++) {
        int lo = jlo[r], hi = jhi[r];
        for (int j0 = lo; j0 < hi && !done; j0 += 32) {
            int j = j0 + lane;
            bool hit = false;
            if (j < hi) {
                float4 p = P[j];
                float dx = __fsub_rn(qx, p.x);
                float dy = __fsub_rn(qy, p.y);
                float dz = __fsub_rn(qz, p.z);
                float d2 = __fadd_rn(__fadd_rn(__fmul_rn(dx, dx),
                                               __fmul_rn(dy, dy)),
                                     __fmul_rn(dz, dz));
                hit = (d2 <= RAD2);
            }
            unsigned msk = __ballot_sync(0xffffffffu, hit);
            if (hit) {
                int pos = cnt + __popc(msk & ((1u << lane) - 1u));
                if (pos < KMAX) outp[pos] = (float)j;
            }
            cnt += __popc(msk);
            if (cnt >= KMAX) { cnt = KMAX; done = true; }
        }
        if (done) break;
    }
}

// ---------------------------------------------------------------------------
extern "C" void kernel_launch(void* const* d_in, const int* in_sizes, int n_in,
                              void* d_out, int out_size)
{
    const float* locs  = (const float*)d_in[0];
    const float* data  = (const float*)d_in[1];
    const float* qlocs = (const float*)d_in[2];

    const int B = 2;                       // fixed by setup_inputs
    const int N = in_sizes[0] / (B * 3);
    const int C = in_sizes[1] / (B * N);
    const int M = in_sizes[2] / (B * 3);
    if (N > NMAX || B > BMAX) return;      // scratch bound guard (never hit)

    float* out       = (float*)d_out;
    float* out_nlocs = out;
    float* out_ndata = out_nlocs + (size_t)B * N * 3;
    float* out_idxs  = out_ndata + (size_t)B * N * C;
    float* out_nb    = out_idxs  + (size_t)B * N;

    size_t smem = (size_t)(NMAX * 3 + NMAX * 2 + (CMAXF + 1)) * sizeof(float);
    cudaFuncSetAttribute(sort_kernel,
                         cudaFuncAttributeMaxDynamicSharedMemorySize, (int)smem);
    sort_kernel<<<B, 1024, smem>>>(locs, out_idxs, out_nlocs, N);

    const int TPB = 256;
    int C4 = C / 4;
    int Q  = C4 / 4;
    int collideBlocks = (B * M * 32 + TPB - 1) / TPB;
    int gatherBlocks  = (B * N * Q + TPB - 1) / TPB;
    tail_kernel<<<collideBlocks + gatherBlocks, TPB>>>(
        (const float4*)data, qlocs, (float4*)out_ndata, out_nb,
        B, N, C4, M, collideBlocks);
}